// round 1
// baseline (speedup 1.0000x reference)
#include <cuda_runtime.h>
#include <mma.h>
#include <math.h>

using namespace nvcuda;

#define NUM_HEADS 32
#define EMB 4096
#define HEAD_DIM 128
#define BATCH 2
#define SEQ 2048

// Scratch (no allocations allowed): qkv = 2*2048*12288 floats (201MB), y = 67MB
__device__ float g_qkv[(size_t)BATCH * SEQ * 3 * EMB];
__device__ float g_y[(size_t)BATCH * SEQ * EMB];

// ---------------------------------------------------------------------------
// TF32 WMMA GEMM: C[M,N] = A[M,K] @ B[K,N], all row-major, dims divisible by tiles.
// Block 128x128, K-step 32, 8 warps as 2(M)x4(N), warp tile 64x32 (4x2 wmma frags).
// ---------------------------------------------------------------------------
#define BM 128
#define BN 128
#define BKK 32

__global__ void __launch_bounds__(256) gemm_tf32_kernel(
    const float* __restrict__ A, const float* __restrict__ B, float* __restrict__ C,
    int M, int N, int K)
{
    __shared__ float As[BM][BKK + 8];   // ldm 40
    __shared__ float Bs[BKK][BN + 8];   // ldm 136

    const int tid = threadIdx.x;
    const int warpId = tid >> 5;
    const int warpM = warpId >> 2;      // 0..1
    const int warpN = warpId & 3;       // 0..3
    const int bm = blockIdx.y * BM;
    const int bn = blockIdx.x * BN;

    wmma::fragment<wmma::accumulator, 16, 16, 8, float> cf[4][2];
#pragma unroll
    for (int i = 0; i < 4; i++)
#pragma unroll
        for (int j = 0; j < 2; j++)
            wmma::fill_fragment(cf[i][j], 0.0f);

    for (int k0 = 0; k0 < K; k0 += BKK) {
        // A tile: 128x32 floats = 1024 float4
#pragma unroll
        for (int it = 0; it < 4; it++) {
            int idx = tid + it * 256;
            int row = idx >> 3;
            int c4 = idx & 7;
            float4 v = *(const float4*)(A + (size_t)(bm + row) * K + k0 + c4 * 4);
            *(float4*)&As[row][c4 * 4] = v;
        }
        // B tile: 32x128 floats = 1024 float4
#pragma unroll
        for (int it = 0; it < 4; it++) {
            int idx = tid + it * 256;
            int row = idx >> 5;
            int c4 = idx & 31;
            float4 v = *(const float4*)(B + (size_t)(k0 + row) * N + bn + c4 * 4);
            *(float4*)&Bs[row][c4 * 4] = v;
        }
        __syncthreads();

#pragma unroll
        for (int kk = 0; kk < BKK; kk += 8) {
            wmma::fragment<wmma::matrix_a, 16, 16, 8, wmma::precision::tf32, wmma::row_major> af[4];
            wmma::fragment<wmma::matrix_b, 16, 16, 8, wmma::precision::tf32, wmma::row_major> bf[2];
#pragma unroll
            for (int i = 0; i < 4; i++) {
                wmma::load_matrix_sync(af[i], &As[warpM * 64 + i * 16][kk], BKK + 8);
#pragma unroll
                for (int t = 0; t < af[i].num_elements; t++)
                    af[i].x[t] = wmma::__float_to_tf32(af[i].x[t]);
            }
#pragma unroll
            for (int j = 0; j < 2; j++) {
                wmma::load_matrix_sync(bf[j], &Bs[kk][warpN * 32 + j * 16], BN + 8);
#pragma unroll
                for (int t = 0; t < bf[j].num_elements; t++)
                    bf[j].x[t] = wmma::__float_to_tf32(bf[j].x[t]);
            }
#pragma unroll
            for (int i = 0; i < 4; i++)
#pragma unroll
                for (int j = 0; j < 2; j++)
                    wmma::mma_sync(cf[i][j], af[i], bf[j], cf[i][j]);
        }
        __syncthreads();
    }

#pragma unroll
    for (int i = 0; i < 4; i++)
#pragma unroll
        for (int j = 0; j < 2; j++) {
            size_t row = (size_t)bm + warpM * 64 + i * 16;
            size_t col = (size_t)bn + warpN * 32 + j * 16;
            wmma::store_matrix_sync(C + row * N + col, cf[i][j], N, wmma::mem_row_major);
        }
}

// ---------------------------------------------------------------------------
// RoPE: in-place on q and k halves of qkv. One thread per (b,s,{q,k},h,d2) pair.
// ---------------------------------------------------------------------------
__global__ void __launch_bounds__(256) rope_kernel(
    float* __restrict__ qkv, const float* __restrict__ fcos, const float* __restrict__ fsin)
{
    int idx = blockIdx.x * blockDim.x + threadIdx.x;
    int d2 = idx & 63;
    int h  = (idx >> 6) & (NUM_HEADS - 1);
    int qk = (idx >> 11) & 1;
    int s  = (idx >> 12) & (SEQ - 1);
    int b  = idx >> 23;
    float c  = fcos[s * 64 + d2];
    float sn = fsin[s * 64 + d2];
    float2* p = (float2*)(qkv + ((size_t)(b * SEQ + s)) * 3 * EMB + qk * EMB + h * HEAD_DIM) + d2;
    float2 v = *p;
    float2 o;
    o.x = v.x * c - v.y * sn;
    o.y = v.x * sn + v.y * c;
    *p = o;
}

// ---------------------------------------------------------------------------
// Flash attention (fp32 SIMT, online softmax), causal.
// Block: one (b, h, q-tile of 64). 256 threads.
// s-phase: thread (ty=tid/16, tx=tid%16) computes s[ty*4+r][tx+16c], r,c in 0..3
// pv-phase: same rows, d columns tx+16cc, cc in 0..7 -> acc[4][8]
// ---------------------------------------------------------------------------
#define BQ 64
#define BKT 64
#define QSTRIDE (HEAD_DIM + 4)   // 132 (float4-aligned rows, reduced conflicts)
#define SSTRIDE (BKT + 4)        // 68

#define FLASH_SMEM_FLOATS (3 * BQ * QSTRIDE + BQ * SSTRIDE + 3 * BQ + 8 * BQ)
#define FLASH_SMEM_BYTES (FLASH_SMEM_FLOATS * 4)

__global__ void __launch_bounds__(256) flash_kernel(
    const float* __restrict__ qkv, float* __restrict__ y)
{
    extern __shared__ float sm[];
    float* qs = sm;                          // 64*132
    float* ks = qs + BQ * QSTRIDE;           // 64*132
    float* vs = ks + BKT * QSTRIDE;          // 64*132
    float* ss = vs + BKT * QSTRIDE;          // 64*68
    float* rowm = ss + BQ * SSTRIDE;         // 64
    float* rowl = rowm + BQ;                 // 64
    float* rowscale = rowl + BQ;             // 64
    float* redmax = rowscale + BQ;           // 4*64
    float* redsum = redmax + 4 * BQ;         // 4*64

    const int tid = threadIdx.x;
    const int qt = blockIdx.x;
    const int h = blockIdx.y;
    const int b = blockIdx.z;
    const int q0 = qt * BQ;

    const int tx = tid & 15;
    const int ty = tid >> 4;

    const size_t rowstride = 3 * EMB;
    const float* qbase  = qkv + ((size_t)(b * SEQ + q0)) * rowstride + h * HEAD_DIM;
    const float* kbase0 = qkv + ((size_t)b * SEQ) * rowstride + EMB + h * HEAD_DIM;
    const float* vbase0 = kbase0 + EMB;

    // load q tile: 64x128 = 2048 float4
#pragma unroll
    for (int it = 0; it < 8; it++) {
        int idx = tid + it * 256;
        int row = idx >> 5;
        int c4 = idx & 31;
        float4 v = *(const float4*)(qbase + (size_t)row * rowstride + c4 * 4);
        *(float4*)&qs[row * QSTRIDE + c4 * 4] = v;
    }
    if (tid < BQ) {
        rowm[tid] = -INFINITY;
        rowl[tid] = 0.0f;
    }

    float acc[4][8];
#pragma unroll
    for (int r = 0; r < 4; r++)
#pragma unroll
        for (int c = 0; c < 8; c++)
            acc[r][c] = 0.0f;

    const float smscale = 0.08838834764831845f;  // 1/sqrt(128)

    for (int kt = 0; kt <= qt; kt++) {
        __syncthreads();  // q visible (iter 0); ks/vs/ss free to overwrite (iter>0)
        const float* kbase = kbase0 + (size_t)kt * BKT * rowstride;
        const float* vbase = vbase0 + (size_t)kt * BKT * rowstride;
#pragma unroll
        for (int it = 0; it < 8; it++) {
            int idx = tid + it * 256;
            int row = idx >> 5;
            int c4 = idx & 31;
            *(float4*)&ks[row * QSTRIDE + c4 * 4] =
                *(const float4*)(kbase + (size_t)row * rowstride + c4 * 4);
            *(float4*)&vs[row * QSTRIDE + c4 * 4] =
                *(const float4*)(vbase + (size_t)row * rowstride + c4 * 4);
        }
        __syncthreads();

        // s = (q @ k^T) * scale, causal-masked
        float sacc[4][4] = {};
#pragma unroll 4
        for (int kk = 0; kk < HEAD_DIM; kk += 4) {
            float4 qv[4], kv[4];
#pragma unroll
            for (int r = 0; r < 4; r++)
                qv[r] = *(const float4*)&qs[(ty * 4 + r) * QSTRIDE + kk];
#pragma unroll
            for (int c = 0; c < 4; c++)
                kv[c] = *(const float4*)&ks[(tx + 16 * c) * QSTRIDE + kk];
#pragma unroll
            for (int r = 0; r < 4; r++)
#pragma unroll
                for (int c = 0; c < 4; c++) {
                    sacc[r][c] = fmaf(qv[r].x, kv[c].x, sacc[r][c]);
                    sacc[r][c] = fmaf(qv[r].y, kv[c].y, sacc[r][c]);
                    sacc[r][c] = fmaf(qv[r].z, kv[c].z, sacc[r][c]);
                    sacc[r][c] = fmaf(qv[r].w, kv[c].w, sacc[r][c]);
                }
        }
#pragma unroll
        for (int r = 0; r < 4; r++) {
            int qr = ty * 4 + r;
            int qglob = q0 + qr;
#pragma unroll
            for (int c = 0; c < 4; c++) {
                int kc = tx + 16 * c;
                int kglob = kt * BKT + kc;
                float val = sacc[r][c] * smscale;
                if (kglob > qglob) val = -INFINITY;
                ss[qr * SSTRIDE + kc] = val;
            }
        }
        __syncthreads();

        // pass 1: partial row max (4 threads per row)
        {
            int row = tid >> 2;
            int part = tid & 3;
            float m = -INFINITY;
#pragma unroll
            for (int j = 0; j < 16; j++)
                m = fmaxf(m, ss[row * SSTRIDE + part * 16 + j]);
            redmax[part * BQ + row] = m;
        }
        __syncthreads();
        if (tid < BQ) {
            float mold = rowm[tid];
            float mnew = fmaxf(fmaxf(redmax[tid], redmax[BQ + tid]),
                               fmaxf(redmax[2 * BQ + tid], redmax[3 * BQ + tid]));
            mnew = fmaxf(mold, mnew);
            rowscale[tid] = __expf(mold - mnew);
            rowm[tid] = mnew;
        }
        __syncthreads();
        // pass 2: p = exp(s - m), partial sums, write p back into ss
        {
            int row = tid >> 2;
            int part = tid & 3;
            float m = rowm[row];
            float sum = 0.0f;
#pragma unroll
            for (int j = 0; j < 16; j++) {
                float p = __expf(ss[row * SSTRIDE + part * 16 + j] - m);
                ss[row * SSTRIDE + part * 16 + j] = p;
                sum += p;
            }
            redsum[part * BQ + row] = sum;
        }
        __syncthreads();
        if (tid < BQ) {
            float s4 = redsum[tid] + redsum[BQ + tid] + redsum[2 * BQ + tid] + redsum[3 * BQ + tid];
            rowl[tid] = rowl[tid] * rowscale[tid] + s4;
        }
        __syncthreads();

        // rescale acc, then acc += p @ v
        float scr[4];
#pragma unroll
        for (int r = 0; r < 4; r++) scr[r] = rowscale[ty * 4 + r];
#pragma unroll
        for (int r = 0; r < 4; r++)
#pragma unroll
            for (int c = 0; c < 8; c++)
                acc[r][c] *= scr[r];

        for (int k = 0; k < BKT; k++) {
            float pr[4];
#pragma unroll
            for (int r = 0; r < 4; r++)
                pr[r] = ss[(ty * 4 + r) * SSTRIDE + k];
#pragma unroll
            for (int c = 0; c < 8; c++) {
                float vv = vs[k * QSTRIDE + tx + 16 * c];
#pragma unroll
                for (int r = 0; r < 4; r++)
                    acc[r][c] = fmaf(pr[r], vv, acc[r][c]);
            }
        }
    }

    // write y[b, q, h*128 + d] = acc / l
#pragma unroll
    for (int r = 0; r < 4; r++) {
        int qr = ty * 4 + r;
        float inv = 1.0f / rowl[qr];
        size_t obase = ((size_t)(b * SEQ + q0 + qr)) * EMB + h * HEAD_DIM;
#pragma unroll
        for (int c = 0; c < 8; c++)
            y[obase + tx + 16 * c] = acc[r][c] * inv;
    }
}

// ---------------------------------------------------------------------------
// Launch
// ---------------------------------------------------------------------------
extern "C" void kernel_launch(void* const* d_in, const int* in_sizes, int n_in,
                              void* d_out, int out_size)
{
    const float* x       = (const float*)d_in[0];
    const float* w_atten = (const float*)d_in[1];
    const float* w_proj  = (const float*)d_in[2];
    const float* fcos    = (const float*)d_in[3];
    const float* fsin    = (const float*)d_in[4];
    float* out = (float*)d_out;

    float* qkv = nullptr;
    float* y = nullptr;
    cudaGetSymbolAddress((void**)&qkv, g_qkv);
    cudaGetSymbolAddress((void**)&y, g_y);

    // 1) qkv = x @ w_atten : [4096, 4096] @ [4096, 12288]
    {
        dim3 grid((3 * EMB) / BN, (BATCH * SEQ) / BM);
        gemm_tf32_kernel<<<grid, 256>>>(x, w_atten, qkv, BATCH * SEQ, 3 * EMB, EMB);
    }

    // 2) RoPE on q and k halves, in place
    {
        int pairs = BATCH * SEQ * 2 * NUM_HEADS * (HEAD_DIM / 2);  // 16.7M
        rope_kernel<<<pairs / 256, 256>>>(qkv, fcos, fsin);
    }

    // 3) causal flash attention -> y [B, S, E]
    {
        cudaFuncSetAttribute(flash_kernel, cudaFuncAttributeMaxDynamicSharedMemorySize,
                             FLASH_SMEM_BYTES);
        dim3 grid(SEQ / BQ, NUM_HEADS, BATCH);
        flash_kernel<<<grid, 256, FLASH_SMEM_BYTES>>>(qkv, y);
    }

    // 4) out = y @ w_proj : [4096, 4096] @ [4096, 4096]
    {
        dim3 grid(EMB / BN, (BATCH * SEQ) / BM);
        gemm_tf32_kernel<<<grid, 256>>>(y, w_proj, out, BATCH * SEQ, EMB, EMB);
    }
}

// round 2
// speedup vs baseline: 1.0348x; 1.0348x over previous
#include <cuda_runtime.h>
#include <mma.h>
#include <math.h>

using namespace nvcuda;

#define NUM_HEADS 32
#define EMB 4096
#define HEAD_DIM 128
#define BATCH 2
#define SEQ 2048

// Scratch (no allocations allowed)
__device__ float g_qkv[(size_t)BATCH * SEQ * 3 * EMB];
__device__ float g_y[(size_t)BATCH * SEQ * EMB];

__device__ __forceinline__ unsigned f2t(float x) {
    unsigned u;
    asm("cvt.rna.tf32.f32 %0, %1;" : "=r"(u) : "f"(x));
    return u;
}

__device__ __forceinline__ void mma_tf32(float* d,
    unsigned a0, unsigned a1, unsigned a2, unsigned a3,
    unsigned b0, unsigned b1)
{
    asm volatile(
        "mma.sync.aligned.m16n8k8.row.col.f32.tf32.tf32.f32 "
        "{%0,%1,%2,%3},{%4,%5,%6,%7},{%8,%9},{%0,%1,%2,%3};\n"
        : "+f"(d[0]), "+f"(d[1]), "+f"(d[2]), "+f"(d[3])
        : "r"(a0), "r"(a1), "r"(a2), "r"(a3), "r"(b0), "r"(b1));
}

// ---------------------------------------------------------------------------
// TF32 WMMA GEMM, double-buffered smem, tf32 conversion at smem store.
// 512 threads, 16 warps as 4(M)x4(N), warp tile 32x32. Block 128x128, K-step 32.
// ---------------------------------------------------------------------------
#define BM 128
#define BN 128
#define BKK 32
#define ASTR 40
#define BSTR 136
#define ATILE (BM * ASTR)    // 5120 floats
#define BTILE (BKK * BSTR)   // 4352 floats
#define GEMM_SMEM_BYTES ((ATILE + BTILE) * 2 * 4)   // 75776

__global__ void __launch_bounds__(512) gemm_tf32_kernel(
    const float* __restrict__ A, const float* __restrict__ B, float* __restrict__ C,
    int M, int N, int K)
{
    extern __shared__ float gsm[];
    float* Asm[2] = { gsm, gsm + ATILE + BTILE };
    float* Bsm[2] = { gsm + ATILE, gsm + 2 * ATILE + BTILE };

    const int tid = threadIdx.x;
    const int wid = tid >> 5;
    const int wM = wid >> 2;   // 0..3
    const int wN = wid & 3;    // 0..3
    const int bm = blockIdx.y * BM;
    const int bn = blockIdx.x * BN;

    wmma::fragment<wmma::accumulator, 16, 16, 8, float> cf[2][2];
#pragma unroll
    for (int i = 0; i < 2; i++)
#pragma unroll
        for (int j = 0; j < 2; j++)
            wmma::fill_fragment(cf[i][j], 0.0f);

    const int arow0 = tid >> 3, ac4 = tid & 7;
    const int brow0 = tid >> 5, bc4 = tid & 31;

    float4 pa[2], pb[2];

    // prologue: load tile k0=0
#pragma unroll
    for (int i = 0; i < 2; i++) {
        pa[i] = *(const float4*)(A + (size_t)(bm + arow0 + i * 64) * K + ac4 * 4);
        pb[i] = *(const float4*)(B + (size_t)(brow0 + i * 16) * N + bn + bc4 * 4);
    }
#pragma unroll
    for (int i = 0; i < 2; i++) {
        float* p = &Asm[0][(arow0 + i * 64) * ASTR + ac4 * 4];
        p[0] = wmma::__float_to_tf32(pa[i].x); p[1] = wmma::__float_to_tf32(pa[i].y);
        p[2] = wmma::__float_to_tf32(pa[i].z); p[3] = wmma::__float_to_tf32(pa[i].w);
        float* q = &Bsm[0][(brow0 + i * 16) * BSTR + bc4 * 4];
        q[0] = wmma::__float_to_tf32(pb[i].x); q[1] = wmma::__float_to_tf32(pb[i].y);
        q[2] = wmma::__float_to_tf32(pb[i].z); q[3] = wmma::__float_to_tf32(pb[i].w);
    }
    __syncthreads();

    int buf = 0;
    for (int k0 = 0; k0 < K; k0 += BKK) {
        const bool more = (k0 + BKK) < K;
        if (more) {
#pragma unroll
            for (int i = 0; i < 2; i++) {
                pa[i] = *(const float4*)(A + (size_t)(bm + arow0 + i * 64) * K + k0 + BKK + ac4 * 4);
                pb[i] = *(const float4*)(B + (size_t)(k0 + BKK + brow0 + i * 16) * N + bn + bc4 * 4);
            }
        }
#pragma unroll
        for (int kk = 0; kk < BKK; kk += 8) {
            wmma::fragment<wmma::matrix_a, 16, 16, 8, wmma::precision::tf32, wmma::row_major> af[2];
            wmma::fragment<wmma::matrix_b, 16, 16, 8, wmma::precision::tf32, wmma::row_major> bf[2];
#pragma unroll
            for (int i = 0; i < 2; i++)
                wmma::load_matrix_sync(af[i], &Asm[buf][(wM * 32 + i * 16) * ASTR + kk], ASTR);
#pragma unroll
            for (int j = 0; j < 2; j++)
                wmma::load_matrix_sync(bf[j], &Bsm[buf][kk * BSTR + wN * 32 + j * 16], BSTR);
#pragma unroll
            for (int i = 0; i < 2; i++)
#pragma unroll
                for (int j = 0; j < 2; j++)
                    wmma::mma_sync(cf[i][j], af[i], bf[j], cf[i][j]);
        }
        if (more) {
            int nb = buf ^ 1;
#pragma unroll
            for (int i = 0; i < 2; i++) {
                float* p = &Asm[nb][(arow0 + i * 64) * ASTR + ac4 * 4];
                p[0] = wmma::__float_to_tf32(pa[i].x); p[1] = wmma::__float_to_tf32(pa[i].y);
                p[2] = wmma::__float_to_tf32(pa[i].z); p[3] = wmma::__float_to_tf32(pa[i].w);
                float* q = &Bsm[nb][(brow0 + i * 16) * BSTR + bc4 * 4];
                q[0] = wmma::__float_to_tf32(pb[i].x); q[1] = wmma::__float_to_tf32(pb[i].y);
                q[2] = wmma::__float_to_tf32(pb[i].z); q[3] = wmma::__float_to_tf32(pb[i].w);
            }
        }
        __syncthreads();
        buf ^= 1;
    }

#pragma unroll
    for (int i = 0; i < 2; i++)
#pragma unroll
        for (int j = 0; j < 2; j++) {
            size_t row = (size_t)bm + wM * 32 + i * 16;
            size_t col = (size_t)bn + wN * 32 + j * 16;
            wmma::store_matrix_sync(C + row * N + col, cf[i][j], N, wmma::mem_row_major);
        }
}

// ---------------------------------------------------------------------------
// RoPE: in-place on q and k halves of qkv.
// ---------------------------------------------------------------------------
__global__ void __launch_bounds__(256) rope_kernel(
    float* __restrict__ qkv, const float* __restrict__ fcos, const float* __restrict__ fsin)
{
    int idx = blockIdx.x * blockDim.x + threadIdx.x;
    int d2 = idx & 63;
    int h  = (idx >> 6) & (NUM_HEADS - 1);
    int qk = (idx >> 11) & 1;
    int s  = (idx >> 12) & (SEQ - 1);
    int b  = idx >> 23;
    float c  = fcos[s * 64 + d2];
    float sn = fsin[s * 64 + d2];
    float2* p = (float2*)(qkv + ((size_t)(b * SEQ + s)) * 3 * EMB + qk * EMB + h * HEAD_DIM) + d2;
    float2 v = *p;
    float2 o;
    o.x = v.x * c - v.y * sn;
    o.y = v.x * sn + v.y * c;
    *p = o;
}

// ---------------------------------------------------------------------------
// Flash attention on tensor cores (mma.sync m16n8k8 tf32), causal, online softmax.
// BQ=128, BK=64, 8 warps (warp w owns q rows 16w..16w+15). Stats in registers.
// ---------------------------------------------------------------------------
#define FBQ 128
#define FBK 64
#define QSTR 132
#define PSTR 68
#define FLASH_SMEM_BYTES ((FBQ * QSTR + 2 * FBK * QSTR + FBQ * PSTR) * 4)  // 169984

__global__ void __launch_bounds__(256) flash_mma_kernel(
    const float* __restrict__ qkv, float* __restrict__ y)
{
    extern __shared__ unsigned fsm[];
    unsigned* qs = fsm;
    unsigned* ks = qs + FBQ * QSTR;
    unsigned* vs = ks + FBK * QSTR;
    unsigned* ps = vs + FBK * QSTR;

    const int tid = threadIdx.x;
    const int w = tid >> 5;
    const int l = tid & 31;
    const int lq = l >> 2;
    const int lr = l & 3;
    const int qt = blockIdx.x;
    const int h = blockIdx.y;
    const int b = blockIdx.z;
    const int q0 = qt * FBQ;

    const size_t rs = 3 * EMB;
    const float* qb  = qkv + (size_t)(b * SEQ + q0) * rs + h * HEAD_DIM;
    const float* kb0 = qkv + (size_t)(b * SEQ) * rs + EMB + h * HEAD_DIM;
    const float* vb0 = kb0 + EMB;

#pragma unroll
    for (int i = 0; i < 16; i++) {
        int idx = tid + i * 256;
        int row = idx >> 5, c4 = idx & 31;
        float4 v = *(const float4*)(qb + (size_t)row * rs + c4 * 4);
        *(uint4*)&qs[row * QSTR + c4 * 4] = make_uint4(f2t(v.x), f2t(v.y), f2t(v.z), f2t(v.w));
    }

    float d[16][4];
#pragma unroll
    for (int nt = 0; nt < 16; nt++)
#pragma unroll
        for (int c = 0; c < 4; c++)
            d[nt][c] = 0.0f;

    float m0 = -INFINITY, m1 = -INFINITY, l0 = 0.0f, l1 = 0.0f;
    const float sc = 0.08838834764831845f;
    const int ktmax = 2 * qt + 1;
    const int myrowmax = q0 + w * 16 + 15;
    const int arow = w * 16 + lq;

    for (int kt = 0; kt <= ktmax; kt++) {
        __syncthreads();
        const float* kb = kb0 + (size_t)kt * FBK * rs;
        const float* vb = vb0 + (size_t)kt * FBK * rs;
#pragma unroll
        for (int i = 0; i < 8; i++) {
            int idx = tid + i * 256;
            int row = idx >> 5, c4 = idx & 31;
            float4 kv = *(const float4*)(kb + (size_t)row * rs + c4 * 4);
            float4 vv = *(const float4*)(vb + (size_t)row * rs + c4 * 4);
            *(uint4*)&ks[row * QSTR + c4 * 4] = make_uint4(f2t(kv.x), f2t(kv.y), f2t(kv.z), f2t(kv.w));
            *(uint4*)&vs[row * QSTR + c4 * 4] = make_uint4(f2t(vv.x), f2t(vv.y), f2t(vv.z), f2t(vv.w));
        }
        __syncthreads();

        const bool active = (kt * FBK <= myrowmax);
        if (active) {
            float s[8][4];
#pragma unroll
            for (int nt = 0; nt < 8; nt++)
#pragma unroll
                for (int c = 0; c < 4; c++)
                    s[nt][c] = 0.0f;

#pragma unroll
            for (int k = 0; k < 16; k++) {
                const int k0 = k * 8;
                unsigned a0 = qs[arow * QSTR + k0 + lr];
                unsigned a1 = qs[(arow + 8) * QSTR + k0 + lr];
                unsigned a2 = qs[arow * QSTR + k0 + lr + 4];
                unsigned a3 = qs[(arow + 8) * QSTR + k0 + lr + 4];
#pragma unroll
                for (int nt = 0; nt < 8; nt++) {
                    unsigned b0 = ks[(nt * 8 + lq) * QSTR + k0 + lr];
                    unsigned b1 = ks[(nt * 8 + lq) * QSTR + k0 + lr + 4];
                    mma_tf32(s[nt], a0, a1, a2, a3, b0, b1);
                }
            }

            const bool domask = (kt >= 2 * qt);
#pragma unroll
            for (int nt = 0; nt < 8; nt++)
#pragma unroll
                for (int c = 0; c < 4; c++) {
                    float v = s[nt][c] * sc;
                    if (domask) {
                        int kg = kt * FBK + nt * 8 + 2 * lr + (c & 1);
                        int rg = q0 + arow + ((c >= 2) ? 8 : 0);
                        if (kg > rg) v = -INFINITY;
                    }
                    s[nt][c] = v;
                }

            float mx0 = -INFINITY, mx1 = -INFINITY;
#pragma unroll
            for (int nt = 0; nt < 8; nt++) {
                mx0 = fmaxf(mx0, fmaxf(s[nt][0], s[nt][1]));
                mx1 = fmaxf(mx1, fmaxf(s[nt][2], s[nt][3]));
            }
            mx0 = fmaxf(mx0, __shfl_xor_sync(0xffffffffu, mx0, 1));
            mx0 = fmaxf(mx0, __shfl_xor_sync(0xffffffffu, mx0, 2));
            mx1 = fmaxf(mx1, __shfl_xor_sync(0xffffffffu, mx1, 1));
            mx1 = fmaxf(mx1, __shfl_xor_sync(0xffffffffu, mx1, 2));

            float nm0 = fmaxf(m0, mx0), nm1 = fmaxf(m1, mx1);
            float al0 = __expf(m0 - nm0), al1 = __expf(m1 - nm1);
            m0 = nm0; m1 = nm1;

            float sum0 = 0.0f, sum1 = 0.0f;
#pragma unroll
            for (int nt = 0; nt < 8; nt++) {
                float p0 = __expf(s[nt][0] - nm0);
                float p1 = __expf(s[nt][1] - nm0);
                float p2 = __expf(s[nt][2] - nm1);
                float p3 = __expf(s[nt][3] - nm1);
                s[nt][0] = p0; s[nt][1] = p1; s[nt][2] = p2; s[nt][3] = p3;
                sum0 += p0 + p1; sum1 += p2 + p3;
            }
            sum0 += __shfl_xor_sync(0xffffffffu, sum0, 1);
            sum0 += __shfl_xor_sync(0xffffffffu, sum0, 2);
            sum1 += __shfl_xor_sync(0xffffffffu, sum1, 1);
            sum1 += __shfl_xor_sync(0xffffffffu, sum1, 2);
            l0 = l0 * al0 + sum0;
            l1 = l1 * al1 + sum1;

#pragma unroll
            for (int nt = 0; nt < 16; nt++) {
                d[nt][0] *= al0; d[nt][1] *= al0;
                d[nt][2] *= al1; d[nt][3] *= al1;
            }

#pragma unroll
            for (int nt = 0; nt < 8; nt++) {
                *(uint2*)&ps[arow * PSTR + nt * 8 + 2 * lr] =
                    make_uint2(f2t(s[nt][0]), f2t(s[nt][1]));
                *(uint2*)&ps[(arow + 8) * PSTR + nt * 8 + 2 * lr] =
                    make_uint2(f2t(s[nt][2]), f2t(s[nt][3]));
            }
        }
        __syncwarp();

        if (active) {
#pragma unroll
            for (int k = 0; k < 8; k++) {
                const int k0 = k * 8;
                unsigned a0 = ps[arow * PSTR + k0 + lr];
                unsigned a1 = ps[(arow + 8) * PSTR + k0 + lr];
                unsigned a2 = ps[arow * PSTR + k0 + lr + 4];
                unsigned a3 = ps[(arow + 8) * PSTR + k0 + lr + 4];
#pragma unroll
                for (int nt = 0; nt < 16; nt++) {
                    unsigned b0 = vs[(k0 + lr) * QSTR + nt * 8 + lq];
                    unsigned b1 = vs[(k0 + lr + 4) * QSTR + nt * 8 + lq];
                    mma_tf32(d[nt], a0, a1, a2, a3, b0, b1);
                }
            }
        }
        __syncwarp();
    }

    float inv0 = 1.0f / l0, inv1 = 1.0f / l1;
    float* yb  = y + (size_t)(b * SEQ + q0 + arow) * EMB + h * HEAD_DIM;
    float* yb2 = yb + (size_t)8 * EMB;
#pragma unroll
    for (int nt = 0; nt < 16; nt++) {
        *(float2*)&yb[nt * 8 + 2 * lr]  = make_float2(d[nt][0] * inv0, d[nt][1] * inv0);
        *(float2*)&yb2[nt * 8 + 2 * lr] = make_float2(d[nt][2] * inv1, d[nt][3] * inv1);
    }
}

// ---------------------------------------------------------------------------
// Launch
// ---------------------------------------------------------------------------
extern "C" void kernel_launch(void* const* d_in, const int* in_sizes, int n_in,
                              void* d_out, int out_size)
{
    const float* x       = (const float*)d_in[0];
    const float* w_atten = (const float*)d_in[1];
    const float* w_proj  = (const float*)d_in[2];
    const float* fcos    = (const float*)d_in[3];
    const float* fsin    = (const float*)d_in[4];
    float* out = (float*)d_out;

    float* qkv = nullptr;
    float* y = nullptr;
    cudaGetSymbolAddress((void**)&qkv, g_qkv);
    cudaGetSymbolAddress((void**)&y, g_y);

    cudaFuncSetAttribute(gemm_tf32_kernel, cudaFuncAttributeMaxDynamicSharedMemorySize,
                         GEMM_SMEM_BYTES);
    cudaFuncSetAttribute(flash_mma_kernel, cudaFuncAttributeMaxDynamicSharedMemorySize,
                         FLASH_SMEM_BYTES);

    // 1) qkv = x @ w_atten
    {
        dim3 grid((3 * EMB) / BN, (BATCH * SEQ) / BM);
        gemm_tf32_kernel<<<grid, 512, GEMM_SMEM_BYTES>>>(x, w_atten, qkv,
                                                         BATCH * SEQ, 3 * EMB, EMB);
    }
    // 2) RoPE
    {
        int pairs = BATCH * SEQ * 2 * NUM_HEADS * (HEAD_DIM / 2);
        rope_kernel<<<pairs / 256, 256>>>(qkv, fcos, fsin);
    }
    // 3) flash attention (tensor cores)
    {
        dim3 grid(SEQ / FBQ, NUM_HEADS, BATCH);
        flash_mma_kernel<<<grid, 256, FLASH_SMEM_BYTES>>>(qkv, y);
    }
    // 4) out = y @ w_proj
    {
        dim3 grid(EMB / BN, (BATCH * SEQ) / BM);
        gemm_tf32_kernel<<<grid, 512, GEMM_SMEM_BYTES>>>(y, w_proj, out, BATCH * SEQ, EMB, EMB);
    }
}

// round 4
// speedup vs baseline: 3.8303x; 3.7016x over previous
#include <cuda_runtime.h>
#include <cuda_fp16.h>
#include <mma.h>
#include <math.h>
#include <stdint.h>

using namespace nvcuda;

#define NUM_HEADS 32
#define EMB 4096
#define HEAD_DIM 128
#define BATCH 2
#define SEQ 2048

// ---------------------------------------------------------------------------
// Scratch (no allocations allowed)
// ---------------------------------------------------------------------------
__device__ float g_qkv[(size_t)BATCH * SEQ * 3 * EMB];     // 201 MB fp32
__device__ float g_y[(size_t)BATCH * SEQ * EMB];           // 67 MB fp32
__device__ __half g_a16[(size_t)BATCH * SEQ * EMB];        // 33.5 MB (x or y in fp16)
__device__ __half g_b16[(size_t)3 * EMB * EMB];            // 100 MB (weights in fp16)

// ---------------------------------------------------------------------------
// fp32 -> fp16 conversion, 8 elements per thread
// ---------------------------------------------------------------------------
__global__ void __launch_bounds__(256) cvt16_kernel(
    const float* __restrict__ in, __half* __restrict__ out)
{
    size_t i = ((size_t)blockIdx.x * 256 + threadIdx.x) * 8;
    float4 v0 = *(const float4*)(in + i);
    float4 v1 = *(const float4*)(in + i + 4);
    __half2 h[4];
    h[0] = __floats2half2_rn(v0.x, v0.y);
    h[1] = __floats2half2_rn(v0.z, v0.w);
    h[2] = __floats2half2_rn(v1.x, v1.y);
    h[3] = __floats2half2_rn(v1.z, v1.w);
    *(uint4*)(out + i) = *(uint4*)h;
}

// ---------------------------------------------------------------------------
// fp16 WMMA GEMM: C[M,N] = A[M,K] @ B[K,N], fp32 accum. Double-buffered.
// 256 threads, 8 warps as 2(M)x4(N), warp tile 64x32. Block 128x128, K-step 32.
// ---------------------------------------------------------------------------
#define BM 128
#define BN 128
#define BK 32
#define AST 40
#define BST 136
#define ATILE (BM * AST)      // 5120 halves
#define BTILE (BK * BST)      // 4352 halves
#define GEMM_SMEM ((ATILE + BTILE) * 2 * 2)   // 37888 bytes

__global__ void __launch_bounds__(256, 2) gemm_f16_kernel(
    const __half* __restrict__ A, const __half* __restrict__ B,
    float* __restrict__ C, int M, int N, int K)
{
    extern __shared__ __half hsm[];
    __half* Asm[2] = { hsm, hsm + ATILE + BTILE };
    __half* Bsm[2] = { hsm + ATILE, hsm + 2 * ATILE + BTILE };

    const int tid = threadIdx.x;
    const int wid = tid >> 5;
    const int wM = wid >> 2;   // 0..1
    const int wN = wid & 3;    // 0..3
    const int bm = blockIdx.y * BM;
    const int bn = blockIdx.x * BN;

    wmma::fragment<wmma::accumulator, 16, 16, 16, float> cf[4][2];
#pragma unroll
    for (int i = 0; i < 4; i++)
#pragma unroll
        for (int j = 0; j < 2; j++)
            wmma::fill_fragment(cf[i][j], 0.0f);

    // A: 512 chunks of 8 halves (128x32): row=idx>>2, c=idx&3, 2 iters
    // B: 512 chunks (32x128): row=idx>>4, c=idx&15, 2 iters
    const int ar = tid >> 2, ac = tid & 3;
    const int br = tid >> 4, bc = tid & 15;

    uint4 pa[2], pb[2];
#pragma unroll
    for (int it = 0; it < 2; it++) {
        pa[it] = *(const uint4*)(A + (size_t)(bm + ar + it * 64) * K + ac * 8);
        pb[it] = *(const uint4*)(B + (size_t)(br + it * 16) * N + bn + bc * 8);
    }
#pragma unroll
    for (int it = 0; it < 2; it++) {
        *(uint4*)&Asm[0][(ar + it * 64) * AST + ac * 8] = pa[it];
        *(uint4*)&Bsm[0][(br + it * 16) * BST + bc * 8] = pb[it];
    }
    __syncthreads();

    int buf = 0;
    for (int k0 = 0; k0 < K; k0 += BK) {
        const bool more = (k0 + BK) < K;
        if (more) {
#pragma unroll
            for (int it = 0; it < 2; it++) {
                pa[it] = *(const uint4*)(A + (size_t)(bm + ar + it * 64) * K + k0 + BK + ac * 8);
                pb[it] = *(const uint4*)(B + (size_t)(k0 + BK + br + it * 16) * N + bn + bc * 8);
            }
        }
#pragma unroll
        for (int kk = 0; kk < BK; kk += 16) {
            wmma::fragment<wmma::matrix_a, 16, 16, 16, __half, wmma::row_major> af[4];
            wmma::fragment<wmma::matrix_b, 16, 16, 16, __half, wmma::row_major> bf[2];
#pragma unroll
            for (int i = 0; i < 4; i++)
                wmma::load_matrix_sync(af[i], &Asm[buf][(wM * 64 + i * 16) * AST + kk], AST);
#pragma unroll
            for (int j = 0; j < 2; j++)
                wmma::load_matrix_sync(bf[j], &Bsm[buf][kk * BST + wN * 32 + j * 16], BST);
#pragma unroll
            for (int i = 0; i < 4; i++)
#pragma unroll
                for (int j = 0; j < 2; j++)
                    wmma::mma_sync(cf[i][j], af[i], bf[j], cf[i][j]);
        }
        if (more) {
            int nb = buf ^ 1;
#pragma unroll
            for (int it = 0; it < 2; it++) {
                *(uint4*)&Asm[nb][(ar + it * 64) * AST + ac * 8] = pa[it];
                *(uint4*)&Bsm[nb][(br + it * 16) * BST + bc * 8] = pb[it];
            }
        }
        __syncthreads();
        buf ^= 1;
    }

#pragma unroll
    for (int i = 0; i < 4; i++)
#pragma unroll
        for (int j = 0; j < 2; j++) {
            size_t row = (size_t)bm + wM * 64 + i * 16;
            size_t col = (size_t)bn + wN * 32 + j * 16;
            wmma::store_matrix_sync(C + row * N + col, cf[i][j], N, wmma::mem_row_major);
        }
}

// ---------------------------------------------------------------------------
// RoPE: in-place on q and k halves of qkv (fp32).
// ---------------------------------------------------------------------------
__global__ void __launch_bounds__(256) rope_kernel(
    float* __restrict__ qkv, const float* __restrict__ fcos, const float* __restrict__ fsin)
{
    int idx = blockIdx.x * blockDim.x + threadIdx.x;
    int d2 = idx & 63;
    int h  = (idx >> 6) & (NUM_HEADS - 1);
    int qk = (idx >> 11) & 1;
    int s  = (idx >> 12) & (SEQ - 1);
    int b  = idx >> 23;
    float c  = fcos[s * 64 + d2];
    float sn = fsin[s * 64 + d2];
    float2* p = (float2*)(qkv + ((size_t)(b * SEQ + s)) * 3 * EMB + qk * EMB + h * HEAD_DIM) + d2;
    float2 v = *p;
    float2 o;
    o.x = v.x * c - v.y * sn;
    o.y = v.x * sn + v.y * c;
    *p = o;
}

// ---------------------------------------------------------------------------
// Flash attention, fp16 mma.sync m16n8k16, causal, online softmax.
// BQ=128, BK=64, 8 warps (warp w owns q rows 16w..16w+15). Stats in registers.
// Layouts (halves): qs[128][136], ks[64][136], vs[64][136], ps[128][72].
// PV B-operand via ldmatrix.x2.trans on vs.
// ---------------------------------------------------------------------------
#define FBQ 128
#define FBK 64
#define QST 136
#define PST 72
#define FLASH_SMEM ((FBQ * QST + 2 * FBK * QST + FBQ * PST) * 2)  // 88064 bytes

__device__ __forceinline__ void mma_f16(float* d,
    uint32_t a0, uint32_t a1, uint32_t a2, uint32_t a3,
    uint32_t b0, uint32_t b1)
{
    asm volatile(
        "mma.sync.aligned.m16n8k16.row.col.f32.f16.f16.f32 "
        "{%0,%1,%2,%3},{%4,%5,%6,%7},{%8,%9},{%0,%1,%2,%3};\n"
        : "+f"(d[0]), "+f"(d[1]), "+f"(d[2]), "+f"(d[3])
        : "r"(a0), "r"(a1), "r"(a2), "r"(a3), "r"(b0), "r"(b1));
}

__device__ __forceinline__ uint32_t smem_u32(const void* p) {
    uint32_t a;
    asm("{ .reg .u64 t; cvta.to.shared.u64 t, %1; cvt.u32.u64 %0, t; }"
        : "=r"(a) : "l"(p));
    return a;
}

__global__ void __launch_bounds__(256) flash_f16_kernel(
    const float* __restrict__ qkv, float* __restrict__ y)
{
    extern __shared__ __half fsm[];
    __half* qs = fsm;                       // 128 x 136
    __half* ks = qs + FBQ * QST;            // 64 x 136
    __half* vs = ks + FBK * QST;            // 64 x 136
    __half* ps = vs + FBK * QST;            // 128 x 72

    const int tid = threadIdx.x;
    const int w = tid >> 5;
    const int l = tid & 31;
    const int lq = l >> 2;   // 0..7
    const int lr = l & 3;    // 0..3
    const int qt = blockIdx.x;
    const int h = blockIdx.y;
    const int b = blockIdx.z;
    const int q0 = qt * FBQ;

    const size_t rs = 3 * EMB;
    const float* qb  = qkv + (size_t)(b * SEQ + q0) * rs + h * HEAD_DIM;
    const float* kb0 = qkv + (size_t)(b * SEQ) * rs + EMB + h * HEAD_DIM;
    const float* vb0 = kb0 + EMB;

    const uint32_t vsu = smem_u32(vs);

    // stage Q: 128 rows x 16 chunks of 8 halves = 2048 chunks, 8 iters
#pragma unroll
    for (int i = 0; i < 8; i++) {
        int idx = tid + i * 256;
        int row = idx >> 4, c = idx & 15;
        float4 v0 = *(const float4*)(qb + (size_t)row * rs + c * 8);
        float4 v1 = *(const float4*)(qb + (size_t)row * rs + c * 8 + 4);
        __half2 hh[4];
        hh[0] = __floats2half2_rn(v0.x, v0.y);
        hh[1] = __floats2half2_rn(v0.z, v0.w);
        hh[2] = __floats2half2_rn(v1.x, v1.y);
        hh[3] = __floats2half2_rn(v1.z, v1.w);
        *(uint4*)&qs[row * QST + c * 8] = *(uint4*)hh;
    }

    float d[16][4];
#pragma unroll
    for (int nt = 0; nt < 16; nt++)
#pragma unroll
        for (int c = 0; c < 4; c++)
            d[nt][c] = 0.0f;

    float m0 = -INFINITY, m1 = -INFINITY, l0 = 0.0f, l1 = 0.0f;
    const float sc = 0.08838834764831845f;  // 1/sqrt(128)
    const int ktmax = 2 * qt + 1;
    const int myrowmax = q0 + w * 16 + 15;
    const int arow = w * 16 + lq;

    for (int kt = 0; kt <= ktmax; kt++) {
        __syncthreads();
        const float* kb = kb0 + (size_t)kt * FBK * rs;
        const float* vb = vb0 + (size_t)kt * FBK * rs;
        // K and V tiles: 64 rows x 16 chunks = 1024 chunks each, 4 iters each
#pragma unroll
        for (int i = 0; i < 4; i++) {
            int idx = tid + i * 256;
            int row = idx >> 4, c = idx & 15;
            float4 k0v = *(const float4*)(kb + (size_t)row * rs + c * 8);
            float4 k1v = *(const float4*)(kb + (size_t)row * rs + c * 8 + 4);
            float4 u0v = *(const float4*)(vb + (size_t)row * rs + c * 8);
            float4 u1v = *(const float4*)(vb + (size_t)row * rs + c * 8 + 4);
            __half2 hk[4], hv[4];
            hk[0] = __floats2half2_rn(k0v.x, k0v.y);
            hk[1] = __floats2half2_rn(k0v.z, k0v.w);
            hk[2] = __floats2half2_rn(k1v.x, k1v.y);
            hk[3] = __floats2half2_rn(k1v.z, k1v.w);
            hv[0] = __floats2half2_rn(u0v.x, u0v.y);
            hv[1] = __floats2half2_rn(u0v.z, u0v.w);
            hv[2] = __floats2half2_rn(u1v.x, u1v.y);
            hv[3] = __floats2half2_rn(u1v.z, u1v.w);
            *(uint4*)&ks[row * QST + c * 8] = *(uint4*)hk;
            *(uint4*)&vs[row * QST + c * 8] = *(uint4*)hv;
        }
        __syncthreads();

        const bool active = (kt * FBK <= myrowmax);
        if (active) {
            // ---- S = Q @ K^T ----
            float s[8][4];
#pragma unroll
            for (int nt = 0; nt < 8; nt++)
#pragma unroll
                for (int c = 0; c < 4; c++)
                    s[nt][c] = 0.0f;

#pragma unroll
            for (int k = 0; k < 8; k++) {
                const int k0 = k * 16;
                uint32_t a0 = *(const uint32_t*)&qs[arow * QST + k0 + 2 * lr];
                uint32_t a1 = *(const uint32_t*)&qs[(arow + 8) * QST + k0 + 2 * lr];
                uint32_t a2 = *(const uint32_t*)&qs[arow * QST + k0 + 2 * lr + 8];
                uint32_t a3 = *(const uint32_t*)&qs[(arow + 8) * QST + k0 + 2 * lr + 8];
#pragma unroll
                for (int nt = 0; nt < 8; nt++) {
                    uint32_t b0 = *(const uint32_t*)&ks[(nt * 8 + lq) * QST + k0 + 2 * lr];
                    uint32_t b1 = *(const uint32_t*)&ks[(nt * 8 + lq) * QST + k0 + 2 * lr + 8];
                    mma_f16(s[nt], a0, a1, a2, a3, b0, b1);
                }
            }

            // ---- scale + causal mask ----
            const bool domask = (kt >= 2 * qt);
#pragma unroll
            for (int nt = 0; nt < 8; nt++)
#pragma unroll
                for (int c = 0; c < 4; c++) {
                    float v = s[nt][c] * sc;
                    if (domask) {
                        int kg = kt * FBK + nt * 8 + 2 * lr + (c & 1);
                        int rg = q0 + arow + ((c >= 2) ? 8 : 0);
                        if (kg > rg) v = -INFINITY;
                    }
                    s[nt][c] = v;
                }

            // ---- online softmax (rows arow, arow+8) ----
            float mx0 = -INFINITY, mx1 = -INFINITY;
#pragma unroll
            for (int nt = 0; nt < 8; nt++) {
                mx0 = fmaxf(mx0, fmaxf(s[nt][0], s[nt][1]));
                mx1 = fmaxf(mx1, fmaxf(s[nt][2], s[nt][3]));
            }
            mx0 = fmaxf(mx0, __shfl_xor_sync(0xffffffffu, mx0, 1));
            mx0 = fmaxf(mx0, __shfl_xor_sync(0xffffffffu, mx0, 2));
            mx1 = fmaxf(mx1, __shfl_xor_sync(0xffffffffu, mx1, 1));
            mx1 = fmaxf(mx1, __shfl_xor_sync(0xffffffffu, mx1, 2));

            float nm0 = fmaxf(m0, mx0), nm1 = fmaxf(m1, mx1);
            float al0 = __expf(m0 - nm0), al1 = __expf(m1 - nm1);
            m0 = nm0; m1 = nm1;

            float sum0 = 0.0f, sum1 = 0.0f;
#pragma unroll
            for (int nt = 0; nt < 8; nt++) {
                float p0 = __expf(s[nt][0] - nm0);
                float p1 = __expf(s[nt][1] - nm0);
                float p2 = __expf(s[nt][2] - nm1);
                float p3 = __expf(s[nt][3] - nm1);
                s[nt][0] = p0; s[nt][1] = p1; s[nt][2] = p2; s[nt][3] = p3;
                sum0 += p0 + p1; sum1 += p2 + p3;
            }
            sum0 += __shfl_xor_sync(0xffffffffu, sum0, 1);
            sum0 += __shfl_xor_sync(0xffffffffu, sum0, 2);
            sum1 += __shfl_xor_sync(0xffffffffu, sum1, 1);
            sum1 += __shfl_xor_sync(0xffffffffu, sum1, 2);
            l0 = l0 * al0 + sum0;
            l1 = l1 * al1 + sum1;

            // rescale O accumulator
#pragma unroll
            for (int nt = 0; nt < 16; nt++) {
                d[nt][0] *= al0; d[nt][1] *= al0;
                d[nt][2] *= al1; d[nt][3] *= al1;
            }

            // write P (fp16 pairs along key) to smem
#pragma unroll
            for (int nt = 0; nt < 8; nt++) {
                __half2 p01 = __floats2half2_rn(s[nt][0], s[nt][1]);
                __half2 p23 = __floats2half2_rn(s[nt][2], s[nt][3]);
                *(uint32_t*)&ps[arow * PST + nt * 8 + 2 * lr] = *(uint32_t*)&p01;
                *(uint32_t*)&ps[(arow + 8) * PST + nt * 8 + 2 * lr] = *(uint32_t*)&p23;
            }
        }
        __syncwarp();

        if (active) {
            // ---- O += P @ V, V B-frags via ldmatrix.trans ----
#pragma unroll
            for (int k = 0; k < 4; k++) {
                const int k0 = k * 16;
                uint32_t a0 = *(const uint32_t*)&ps[arow * PST + k0 + 2 * lr];
                uint32_t a1 = *(const uint32_t*)&ps[(arow + 8) * PST + k0 + 2 * lr];
                uint32_t a2 = *(const uint32_t*)&ps[arow * PST + k0 + 2 * lr + 8];
                uint32_t a3 = *(const uint32_t*)&ps[(arow + 8) * PST + k0 + 2 * lr + 8];
                uint32_t rowaddr = vsu + (uint32_t)((k0 + (l & 15)) * QST * 2);
#pragma unroll
                for (int nt = 0; nt < 16; nt++) {
                    uint32_t b0, b1;
                    asm volatile(
                        "ldmatrix.sync.aligned.m8n8.x2.trans.shared.b16 {%0,%1}, [%2];"
                        : "=r"(b0), "=r"(b1) : "r"(rowaddr + nt * 16));
                    mma_f16(d[nt], a0, a1, a2, a3, b0, b1);
                }
            }
        }
        __syncwarp();
    }

    // epilogue: divide by l, write y[b, q, h*128 + d]
    float inv0 = 1.0f / l0, inv1 = 1.0f / l1;
    float* yb  = y + (size_t)(b * SEQ + q0 + arow) * EMB + h * HEAD_DIM;
    float* yb2 = yb + (size_t)8 * EMB;
#pragma unroll
    for (int nt = 0; nt < 16; nt++) {
        *(float2*)&yb[nt * 8 + 2 * lr]  = make_float2(d[nt][0] * inv0, d[nt][1] * inv0);
        *(float2*)&yb2[nt * 8 + 2 * lr] = make_float2(d[nt][2] * inv1, d[nt][3] * inv1);
    }
}

// ---------------------------------------------------------------------------
// Launch
// ---------------------------------------------------------------------------
extern "C" void kernel_launch(void* const* d_in, const int* in_sizes, int n_in,
                              void* d_out, int out_size)
{
    const float* x       = (const float*)d_in[0];
    const float* w_atten = (const float*)d_in[1];
    const float* w_proj  = (const float*)d_in[2];
    const float* fcos    = (const float*)d_in[3];
    const float* fsin    = (const float*)d_in[4];
    float* out = (float*)d_out;

    float* qkv = nullptr;
    float* y = nullptr;
    __half *a16 = nullptr, *b16 = nullptr;
    cudaGetSymbolAddress((void**)&qkv, g_qkv);
    cudaGetSymbolAddress((void**)&y, g_y);
    cudaGetSymbolAddress((void**)&a16, g_a16);
    cudaGetSymbolAddress((void**)&b16, g_b16);

    cudaFuncSetAttribute(gemm_f16_kernel, cudaFuncAttributeMaxDynamicSharedMemorySize,
                         GEMM_SMEM);
    cudaFuncSetAttribute(flash_f16_kernel, cudaFuncAttributeMaxDynamicSharedMemorySize,
                         FLASH_SMEM);

    const int MROWS = BATCH * SEQ;                    // 4096
    const size_t NE = (size_t)MROWS * EMB;            // 16.7M
    const size_t NW1 = (size_t)EMB * 3 * EMB;         // 50.3M

    // 1) convert x and w_atten to fp16
    cvt16_kernel<<<(int)(NE / 2048), 256>>>(x, a16);
    cvt16_kernel<<<(int)(NW1 / 2048), 256>>>(w_atten, b16);

    // 2) qkv = x @ w_atten (fp16 tensor cores, fp32 accum)
    {
        dim3 grid((3 * EMB) / BN, MROWS / BM);
        gemm_f16_kernel<<<grid, 256, GEMM_SMEM>>>(a16, b16, qkv, MROWS, 3 * EMB, EMB);
    }

    // 3) RoPE (fp32, in place)
    {
        int pairs = BATCH * SEQ * 2 * NUM_HEADS * (HEAD_DIM / 2);
        rope_kernel<<<pairs / 256, 256>>>(qkv, fcos, fsin);
    }

    // 4) flash attention (fp16 tensor cores) -> y
    {
        dim3 grid(SEQ / FBQ, NUM_HEADS, BATCH);
        flash_f16_kernel<<<grid, 256, FLASH_SMEM>>>(qkv, y);
    }

    // 5) convert y and w_proj to fp16
    cvt16_kernel<<<(int)(NE / 2048), 256>>>(y, a16);
    cvt16_kernel<<<(int)(NE / 2048), 256>>>(w_proj, b16);

    // 6) out = y @ w_proj
    {
        dim3 grid(EMB / BN, MROWS / BM);
        gemm_f16_kernel<<<grid, 256, GEMM_SMEM>>>(a16, b16, out, MROWS, EMB, EMB);
    }
}

// round 6
// speedup vs baseline: 6.4651x; 1.6879x over previous
#include <cuda_runtime.h>
#include <cuda_fp16.h>
#include <mma.h>
#include <math.h>
#include <stdint.h>

using namespace nvcuda;

#define NUM_HEADS 32
#define EMB 4096
#define HEAD_DIM 128
#define BATCH 2
#define SEQ 2048

// ---------------------------------------------------------------------------
// Scratch (no allocations allowed) — all fp16 activations
// ---------------------------------------------------------------------------
__device__ __half g_qkv16[(size_t)BATCH * SEQ * 3 * EMB];  // 100 MB
__device__ __half g_y16[(size_t)BATCH * SEQ * EMB];        // 33.5 MB
__device__ __half g_a16[(size_t)BATCH * SEQ * EMB];        // 33.5 MB (x fp16)
__device__ __half g_b16[(size_t)3 * EMB * EMB];            // 100 MB (weights fp16)

__device__ __forceinline__ uint32_t smem_u32(const void* p) {
    uint32_t a;
    asm("{ .reg .u64 t; cvta.to.shared.u64 t, %1; cvt.u32.u64 %0, t; }"
        : "=r"(a) : "l"(p));
    return a;
}

#define CP_ASYNC16(saddr, gptr) \
    asm volatile("cp.async.cg.shared.global [%0], [%1], 16;" \
        :: "r"(saddr), "l"(gptr))
#define CP_COMMIT() asm volatile("cp.async.commit_group;")
#define CP_WAIT1()  asm volatile("cp.async.wait_group 1;")
#define CP_WAIT0()  asm volatile("cp.async.wait_group 0;")

// ---------------------------------------------------------------------------
// fp32 -> fp16 conversion, 8 elements per thread
// ---------------------------------------------------------------------------
__global__ void __launch_bounds__(256) cvt16_kernel(
    const float* __restrict__ in, __half* __restrict__ out)
{
    size_t i = ((size_t)blockIdx.x * 256 + threadIdx.x) * 8;
    float4 v0 = *(const float4*)(in + i);
    float4 v1 = *(const float4*)(in + i + 4);
    __half2 h[4];
    h[0] = __floats2half2_rn(v0.x, v0.y);
    h[1] = __floats2half2_rn(v0.z, v0.w);
    h[2] = __floats2half2_rn(v1.x, v1.y);
    h[3] = __floats2half2_rn(v1.z, v1.w);
    *(uint4*)(out + i) = *(uint4*)h;
}

// ---------------------------------------------------------------------------
// fp16 WMMA GEMM, cp.async 3-stage pipeline (one group committed per iter,
// empty groups at tail keep the wait-count invariant exact).
// 256 threads, 8 warps as 2(M)x4(N), warp tile 64x32. Block 128x128, K-step 32.
// MODE 0: output fp16 with fused RoPE (cols < 2*EMB) — for qkv.
// MODE 1: output fp32 plain — for final projection.
// ---------------------------------------------------------------------------
#define BM 128
#define BN 128
#define BK 32
#define AST 40
#define BST 136
#define ATILE (BM * AST)      // 5120 halves
#define BTILE (BK * BST)      // 4352 halves
#define STG (ATILE + BTILE)   // 9472 halves per stage
#define NSTAGE 3
#define GEMM_SMEM (STG * NSTAGE * 2)   // 56832 bytes

template <int MODE>
__global__ void __launch_bounds__(256, 2) gemm_f16_kernel(
    const __half* __restrict__ A, const __half* __restrict__ B,
    void* __restrict__ Cv,
    const float* __restrict__ fcos, const float* __restrict__ fsin,
    int M, int N, int K)
{
    extern __shared__ __half hsm[];
    const uint32_t smb = smem_u32(hsm);

    const int tid = threadIdx.x;
    const int wid = tid >> 5;
    const int l = tid & 31;
    const int wM = wid >> 2;   // 0..1
    const int wN = wid & 3;    // 0..3
    const int bm = blockIdx.y * BM;
    const int bn = blockIdx.x * BN;

    wmma::fragment<wmma::accumulator, 16, 16, 16, float> cf[4][2];
#pragma unroll
    for (int i = 0; i < 4; i++)
#pragma unroll
        for (int j = 0; j < 2; j++)
            wmma::fill_fragment(cf[i][j], 0.0f);

    const int ar = tid >> 2, ac = tid & 3;    // A: rows ar, ar+64; chunk ac
    const int br = tid >> 4, bc = tid & 15;   // B: rows br, br+16; chunk bc

    auto load_stage = [&](int s, int k0) {
        uint32_t abase = smb + (uint32_t)(s * STG) * 2;
        uint32_t bbase = abase + (uint32_t)ATILE * 2;
#pragma unroll
        for (int it = 0; it < 2; it++) {
            CP_ASYNC16(abase + (uint32_t)((ar + it * 64) * AST + ac * 8) * 2,
                       A + (size_t)(bm + ar + it * 64) * K + k0 + ac * 8);
            CP_ASYNC16(bbase + (uint32_t)((br + it * 16) * BST + bc * 8) * 2,
                       B + (size_t)(k0 + br + it * 16) * N + bn + bc * 8);
        }
        CP_COMMIT();
    };

    load_stage(0, 0);
    load_stage(1, BK);

    int st = 0;
    for (int k0 = 0; k0 < K; k0 += BK) {
        CP_WAIT1();
        __syncthreads();
        const __half* As = hsm + st * STG;
        const __half* Bs = As + ATILE;
#pragma unroll
        for (int kk = 0; kk < BK; kk += 16) {
            wmma::fragment<wmma::matrix_a, 16, 16, 16, __half, wmma::row_major> af[4];
            wmma::fragment<wmma::matrix_b, 16, 16, 16, __half, wmma::row_major> bf[2];
#pragma unroll
            for (int i = 0; i < 4; i++)
                wmma::load_matrix_sync(af[i], &As[(wM * 64 + i * 16) * AST + kk], AST);
#pragma unroll
            for (int j = 0; j < 2; j++)
                wmma::load_matrix_sync(bf[j], &Bs[kk * BST + wN * 32 + j * 16], BST);
#pragma unroll
            for (int i = 0; i < 4; i++)
#pragma unroll
                for (int j = 0; j < 2; j++)
                    wmma::mma_sync(cf[i][j], af[i], bf[j], cf[i][j]);
        }
        int kn = k0 + 2 * BK;
        if (kn < K) load_stage(st == 0 ? 2 : st - 1, kn);  // (st+2)%3
        else        CP_COMMIT();   // empty group: keeps one-group-per-iter invariant
        st = (st == 2) ? 0 : st + 1;
        __syncthreads();
    }
    CP_WAIT0();
    __syncthreads();

    if (MODE == 1) {
        float* C = (float*)Cv;
#pragma unroll
        for (int i = 0; i < 4; i++)
#pragma unroll
            for (int j = 0; j < 2; j++) {
                size_t row = (size_t)bm + wM * 64 + i * 16;
                size_t col = (size_t)bn + wN * 32 + j * 16;
                wmma::store_matrix_sync(C + row * N + col, cf[i][j], N, wmma::mem_row_major);
            }
    } else {
        // fp16 output + fused RoPE on q/k column bands
        __half* C = (__half*)Cv;
        float* stage = (float*)hsm + wid * 320;  // 16x20 fp32 per warp
        const bool doRope = (bn < 2 * EMB);
        const int row_l = l >> 1;
        const int ch = (l & 1) * 8;
#pragma unroll
        for (int i = 0; i < 4; i++)
#pragma unroll
            for (int j = 0; j < 2; j++) {
                wmma::store_matrix_sync(stage, cf[i][j], 20, wmma::mem_row_major);
                __syncwarp();
                const float* sp = stage + row_l * 20 + ch;
                int grow = bm + wM * 64 + i * 16 + row_l;
                int gcol = bn + wN * 32 + j * 16 + ch;
                __half hbuf[8];
                if (doRope) {
                    int sidx = grow & (SEQ - 1);
                    int d2b = (gcol & 127) >> 1;
#pragma unroll
                    for (int t = 0; t < 4; t++) {
                        float c = fcos[sidx * 64 + d2b + t];
                        float sn = fsin[sidx * 64 + d2b + t];
                        float xr = sp[2 * t], xi = sp[2 * t + 1];
                        hbuf[2 * t]     = __float2half(xr * c - xi * sn);
                        hbuf[2 * t + 1] = __float2half(xr * sn + xi * c);
                    }
                } else {
#pragma unroll
                    for (int t = 0; t < 8; t++)
                        hbuf[t] = __float2half(sp[t]);
                }
                *(uint4*)(C + (size_t)grow * N + gcol) = *(uint4*)hbuf;
                __syncwarp();
            }
    }
}

// ---------------------------------------------------------------------------
// Flash attention, fp16 mma.sync m16n8k16, causal, online softmax.
// Inputs fp16 (rope already applied), output fp16.
// ---------------------------------------------------------------------------
#define FBQ 128
#define FBK 64
#define QST 136
#define PST 72
#define FLASH_SMEM ((FBQ * QST + 2 * FBK * QST + FBQ * PST) * 2)  // 88064 bytes

__device__ __forceinline__ void mma_f16(float* d,
    uint32_t a0, uint32_t a1, uint32_t a2, uint32_t a3,
    uint32_t b0, uint32_t b1)
{
    asm volatile(
        "mma.sync.aligned.m16n8k16.row.col.f32.f16.f16.f32 "
        "{%0,%1,%2,%3},{%4,%5,%6,%7},{%8,%9},{%0,%1,%2,%3};\n"
        : "+f"(d[0]), "+f"(d[1]), "+f"(d[2]), "+f"(d[3])
        : "r"(a0), "r"(a1), "r"(a2), "r"(a3), "r"(b0), "r"(b1));
}

__global__ void __launch_bounds__(256) flash_f16_kernel(
    const __half* __restrict__ qkv, __half* __restrict__ y)
{
    extern __shared__ __half fsm[];
    __half* qs = fsm;                       // 128 x 136
    __half* ks = qs + FBQ * QST;            // 64 x 136
    __half* vs = ks + FBK * QST;            // 64 x 136
    __half* ps = vs + FBK * QST;            // 128 x 72

    const int tid = threadIdx.x;
    const int w = tid >> 5;
    const int l = tid & 31;
    const int lq = l >> 2;
    const int lr = l & 3;
    const int qt = blockIdx.x;
    const int h = blockIdx.y;
    const int b = blockIdx.z;
    const int q0 = qt * FBQ;

    const size_t rs = 3 * EMB;
    const __half* qb  = qkv + (size_t)(b * SEQ + q0) * rs + h * HEAD_DIM;
    const __half* kb0 = qkv + (size_t)(b * SEQ) * rs + EMB + h * HEAD_DIM;
    const __half* vb0 = kb0 + EMB;

    const uint32_t vsu = smem_u32(vs);

    // stage Q: 128 rows x 16 chunks of 8 halves
#pragma unroll
    for (int i = 0; i < 8; i++) {
        int idx = tid + i * 256;
        int row = idx >> 4, c = idx & 15;
        *(uint4*)&qs[row * QST + c * 8] = *(const uint4*)(qb + (size_t)row * rs + c * 8);
    }

    float d[16][4];
#pragma unroll
    for (int nt = 0; nt < 16; nt++)
#pragma unroll
        for (int c = 0; c < 4; c++)
            d[nt][c] = 0.0f;

    float m0 = -INFINITY, m1 = -INFINITY, l0 = 0.0f, l1 = 0.0f;
    const float sc = 0.08838834764831845f;  // 1/sqrt(128)
    const int ktmax = 2 * qt + 1;
    const int myrowmax = q0 + w * 16 + 15;
    const int arow = w * 16 + lq;

    for (int kt = 0; kt <= ktmax; kt++) {
        __syncthreads();
        const __half* kb = kb0 + (size_t)kt * FBK * rs;
        const __half* vb = vb0 + (size_t)kt * FBK * rs;
#pragma unroll
        for (int i = 0; i < 4; i++) {
            int idx = tid + i * 256;
            int row = idx >> 4, c = idx & 15;
            *(uint4*)&ks[row * QST + c * 8] = *(const uint4*)(kb + (size_t)row * rs + c * 8);
            *(uint4*)&vs[row * QST + c * 8] = *(const uint4*)(vb + (size_t)row * rs + c * 8);
        }
        __syncthreads();

        const bool active = (kt * FBK <= myrowmax);
        if (active) {
            // ---- S = Q @ K^T ----
            float s[8][4];
#pragma unroll
            for (int nt = 0; nt < 8; nt++)
#pragma unroll
                for (int c = 0; c < 4; c++)
                    s[nt][c] = 0.0f;

#pragma unroll
            for (int k = 0; k < 8; k++) {
                const int k0 = k * 16;
                uint32_t a0 = *(const uint32_t*)&qs[arow * QST + k0 + 2 * lr];
                uint32_t a1 = *(const uint32_t*)&qs[(arow + 8) * QST + k0 + 2 * lr];
                uint32_t a2 = *(const uint32_t*)&qs[arow * QST + k0 + 2 * lr + 8];
                uint32_t a3 = *(const uint32_t*)&qs[(arow + 8) * QST + k0 + 2 * lr + 8];
#pragma unroll
                for (int nt = 0; nt < 8; nt++) {
                    uint32_t b0 = *(const uint32_t*)&ks[(nt * 8 + lq) * QST + k0 + 2 * lr];
                    uint32_t b1 = *(const uint32_t*)&ks[(nt * 8 + lq) * QST + k0 + 2 * lr + 8];
                    mma_f16(s[nt], a0, a1, a2, a3, b0, b1);
                }
            }

            // ---- scale + causal mask ----
            const bool domask = (kt >= 2 * qt);
#pragma unroll
            for (int nt = 0; nt < 8; nt++)
#pragma unroll
                for (int c = 0; c < 4; c++) {
                    float v = s[nt][c] * sc;
                    if (domask) {
                        int kg = kt * FBK + nt * 8 + 2 * lr + (c & 1);
                        int rg = q0 + arow + ((c >= 2) ? 8 : 0);
                        if (kg > rg) v = -INFINITY;
                    }
                    s[nt][c] = v;
                }

            // ---- online softmax ----
            float mx0 = -INFINITY, mx1 = -INFINITY;
#pragma unroll
            for (int nt = 0; nt < 8; nt++) {
                mx0 = fmaxf(mx0, fmaxf(s[nt][0], s[nt][1]));
                mx1 = fmaxf(mx1, fmaxf(s[nt][2], s[nt][3]));
            }
            mx0 = fmaxf(mx0, __shfl_xor_sync(0xffffffffu, mx0, 1));
            mx0 = fmaxf(mx0, __shfl_xor_sync(0xffffffffu, mx0, 2));
            mx1 = fmaxf(mx1, __shfl_xor_sync(0xffffffffu, mx1, 1));
            mx1 = fmaxf(mx1, __shfl_xor_sync(0xffffffffu, mx1, 2));

            float nm0 = fmaxf(m0, mx0), nm1 = fmaxf(m1, mx1);
            float al0 = __expf(m0 - nm0), al1 = __expf(m1 - nm1);
            m0 = nm0; m1 = nm1;

            float sum0 = 0.0f, sum1 = 0.0f;
#pragma unroll
            for (int nt = 0; nt < 8; nt++) {
                float p0 = __expf(s[nt][0] - nm0);
                float p1 = __expf(s[nt][1] - nm0);
                float p2 = __expf(s[nt][2] - nm1);
                float p3 = __expf(s[nt][3] - nm1);
                s[nt][0] = p0; s[nt][1] = p1; s[nt][2] = p2; s[nt][3] = p3;
                sum0 += p0 + p1; sum1 += p2 + p3;
            }
            sum0 += __shfl_xor_sync(0xffffffffu, sum0, 1);
            sum0 += __shfl_xor_sync(0xffffffffu, sum0, 2);
            sum1 += __shfl_xor_sync(0xffffffffu, sum1, 1);
            sum1 += __shfl_xor_sync(0xffffffffu, sum1, 2);
            l0 = l0 * al0 + sum0;
            l1 = l1 * al1 + sum1;

#pragma unroll
            for (int nt = 0; nt < 16; nt++) {
                d[nt][0] *= al0; d[nt][1] *= al0;
                d[nt][2] *= al1; d[nt][3] *= al1;
            }

#pragma unroll
            for (int nt = 0; nt < 8; nt++) {
                __half2 p01 = __floats2half2_rn(s[nt][0], s[nt][1]);
                __half2 p23 = __floats2half2_rn(s[nt][2], s[nt][3]);
                *(uint32_t*)&ps[arow * PST + nt * 8 + 2 * lr] = *(uint32_t*)&p01;
                *(uint32_t*)&ps[(arow + 8) * PST + nt * 8 + 2 * lr] = *(uint32_t*)&p23;
            }
        }
        __syncwarp();

        if (active) {
            // ---- O += P @ V (V frags via ldmatrix.trans) ----
#pragma unroll
            for (int k = 0; k < 4; k++) {
                const int k0 = k * 16;
                uint32_t a0 = *(const uint32_t*)&ps[arow * PST + k0 + 2 * lr];
                uint32_t a1 = *(const uint32_t*)&ps[(arow + 8) * PST + k0 + 2 * lr];
                uint32_t a2 = *(const uint32_t*)&ps[arow * PST + k0 + 2 * lr + 8];
                uint32_t a3 = *(const uint32_t*)&ps[(arow + 8) * PST + k0 + 2 * lr + 8];
                uint32_t rowaddr = vsu + (uint32_t)((k0 + (l & 15)) * QST * 2);
#pragma unroll
                for (int nt = 0; nt < 16; nt++) {
                    uint32_t b0, b1;
                    asm volatile(
                        "ldmatrix.sync.aligned.m8n8.x2.trans.shared.b16 {%0,%1}, [%2];"
                        : "=r"(b0), "=r"(b1) : "r"(rowaddr + nt * 16));
                    mma_f16(d[nt], a0, a1, a2, a3, b0, b1);
                }
            }
        }
        __syncwarp();
    }

    // epilogue: divide by l, write fp16 y
    float inv0 = 1.0f / l0, inv1 = 1.0f / l1;
    __half* yb  = y + (size_t)(b * SEQ + q0 + arow) * EMB + h * HEAD_DIM;
    __half* yb2 = yb + (size_t)8 * EMB;
#pragma unroll
    for (int nt = 0; nt < 16; nt++) {
        __half2 o0 = __floats2half2_rn(d[nt][0] * inv0, d[nt][1] * inv0);
        __half2 o1 = __floats2half2_rn(d[nt][2] * inv1, d[nt][3] * inv1);
        *(__half2*)&yb[nt * 8 + 2 * lr]  = o0;
        *(__half2*)&yb2[nt * 8 + 2 * lr] = o1;
    }
}

// ---------------------------------------------------------------------------
// Launch
// ---------------------------------------------------------------------------
extern "C" void kernel_launch(void* const* d_in, const int* in_sizes, int n_in,
                              void* d_out, int out_size)
{
    const float* x       = (const float*)d_in[0];
    const float* w_atten = (const float*)d_in[1];
    const float* w_proj  = (const float*)d_in[2];
    const float* fcos    = (const float*)d_in[3];
    const float* fsin    = (const float*)d_in[4];
    float* out = (float*)d_out;

    __half *qkv16 = nullptr, *y16 = nullptr, *a16 = nullptr, *b16 = nullptr;
    cudaGetSymbolAddress((void**)&qkv16, g_qkv16);
    cudaGetSymbolAddress((void**)&y16, g_y16);
    cudaGetSymbolAddress((void**)&a16, g_a16);
    cudaGetSymbolAddress((void**)&b16, g_b16);

    cudaFuncSetAttribute(gemm_f16_kernel<0>, cudaFuncAttributeMaxDynamicSharedMemorySize,
                         GEMM_SMEM);
    cudaFuncSetAttribute(gemm_f16_kernel<1>, cudaFuncAttributeMaxDynamicSharedMemorySize,
                         GEMM_SMEM);
    cudaFuncSetAttribute(flash_f16_kernel, cudaFuncAttributeMaxDynamicSharedMemorySize,
                         FLASH_SMEM);

    const int MROWS = BATCH * SEQ;                    // 4096
    const size_t NE = (size_t)MROWS * EMB;            // 16.7M
    const size_t NW1 = (size_t)EMB * 3 * EMB;         // 50.3M

    // 1) convert x and w_atten to fp16
    cvt16_kernel<<<(int)(NE / 2048), 256>>>(x, a16);
    cvt16_kernel<<<(int)(NW1 / 2048), 256>>>(w_atten, b16);

    // 2) qkv16 = rope(x @ w_atten) — fused epilogue
    {
        dim3 grid((3 * EMB) / BN, MROWS / BM);
        gemm_f16_kernel<0><<<grid, 256, GEMM_SMEM>>>(a16, b16, qkv16, fcos, fsin,
                                                     MROWS, 3 * EMB, EMB);
    }

    // 3) flash attention -> y16
    {
        dim3 grid(SEQ / FBQ, NUM_HEADS, BATCH);
        flash_f16_kernel<<<grid, 256, FLASH_SMEM>>>(qkv16, y16);
    }

    // 4) convert w_proj, then out = y @ w_proj (fp32 out)
    cvt16_kernel<<<(int)(NE / 2048), 256>>>(w_proj, b16);
    {
        dim3 grid(EMB / BN, MROWS / BM);
        gemm_f16_kernel<1><<<grid, 256, GEMM_SMEM>>>(y16, b16, out, nullptr, nullptr,
                                                     MROWS, EMB, EMB);
    }
}

// round 7
// speedup vs baseline: 6.6019x; 1.0212x over previous
#include <cuda_runtime.h>
#include <cuda_fp16.h>
#include <mma.h>
#include <math.h>
#include <stdint.h>

using namespace nvcuda;

#define NUM_HEADS 32
#define EMB 4096
#define HEAD_DIM 128
#define BATCH 2
#define SEQ 2048

// ---------------------------------------------------------------------------
// Scratch (no allocations allowed) — all fp16 activations
// ---------------------------------------------------------------------------
__device__ __half g_qkv16[(size_t)BATCH * SEQ * 3 * EMB];  // 100 MB
__device__ __half g_y16[(size_t)BATCH * SEQ * EMB];        // 33.5 MB
__device__ __half g_a16[(size_t)BATCH * SEQ * EMB];        // 33.5 MB (x fp16)
__device__ __half g_b16[(size_t)3 * EMB * EMB];            // 100 MB (weights fp16)

__device__ __forceinline__ uint32_t smem_u32(const void* p) {
    uint32_t a;
    asm("{ .reg .u64 t; cvta.to.shared.u64 t, %1; cvt.u32.u64 %0, t; }"
        : "=r"(a) : "l"(p));
    return a;
}

#define CP_ASYNC16(saddr, gptr) \
    asm volatile("cp.async.cg.shared.global [%0], [%1], 16;" \
        :: "r"(saddr), "l"(gptr))
#define CP_COMMIT() asm volatile("cp.async.commit_group;")
#define CP_WAIT1()  asm volatile("cp.async.wait_group 1;")
#define CP_WAIT0()  asm volatile("cp.async.wait_group 0;")

#define LDSM_X4(r0, r1, r2, r3, addr) \
    asm volatile("ldmatrix.sync.aligned.m8n8.x4.shared.b16 {%0,%1,%2,%3}, [%4];" \
        : "=r"(r0), "=r"(r1), "=r"(r2), "=r"(r3) : "r"(addr))
#define LDSM_X4_T(r0, r1, r2, r3, addr) \
    asm volatile("ldmatrix.sync.aligned.m8n8.x4.trans.shared.b16 {%0,%1,%2,%3}, [%4];" \
        : "=r"(r0), "=r"(r1), "=r"(r2), "=r"(r3) : "r"(addr))

// ---------------------------------------------------------------------------
// fp32 -> fp16 conversion, 8 elements per thread
// ---------------------------------------------------------------------------
__global__ void __launch_bounds__(256) cvt16_kernel(
    const float* __restrict__ in, __half* __restrict__ out)
{
    size_t i = ((size_t)blockIdx.x * 256 + threadIdx.x) * 8;
    float4 v0 = *(const float4*)(in + i);
    float4 v1 = *(const float4*)(in + i + 4);
    __half2 h[4];
    h[0] = __floats2half2_rn(v0.x, v0.y);
    h[1] = __floats2half2_rn(v0.z, v0.w);
    h[2] = __floats2half2_rn(v1.x, v1.y);
    h[3] = __floats2half2_rn(v1.z, v1.w);
    *(uint4*)(out + i) = *(uint4*)h;
}

// ---------------------------------------------------------------------------
// fp16 WMMA GEMM, cp.async 3-stage pipeline, 128 threads, 4 warps as 2x2,
// warp tile 64x64 (4x4 wmma frags). Block 128x128, K-step 32.
// MODE 0: output fp16 with fused RoPE (cols < 2*EMB). MODE 1: fp32 plain.
// ---------------------------------------------------------------------------
#define BM 128
#define BN 128
#define BK 32
#define AST 40
#define BST 136
#define ATILE (BM * AST)      // 5120 halves
#define BTILE (BK * BST)      // 4352 halves
#define STG (ATILE + BTILE)   // 9472 halves per stage
#define NSTAGE 3
#define GEMM_SMEM (STG * NSTAGE * 2)   // 56832 bytes

template <int MODE>
__global__ void __launch_bounds__(128, 2) gemm_f16_kernel(
    const __half* __restrict__ A, const __half* __restrict__ B,
    void* __restrict__ Cv,
    const float* __restrict__ fcos, const float* __restrict__ fsin,
    int M, int N, int K)
{
    extern __shared__ __half hsm[];
    const uint32_t smb = smem_u32(hsm);

    const int tid = threadIdx.x;
    const int wid = tid >> 5;
    const int l = tid & 31;
    const int wM = wid >> 1;   // 0..1
    const int wN = wid & 1;    // 0..1
    const int bm = blockIdx.y * BM;
    const int bn = blockIdx.x * BN;

    wmma::fragment<wmma::accumulator, 16, 16, 16, float> cf[4][4];
#pragma unroll
    for (int i = 0; i < 4; i++)
#pragma unroll
        for (int j = 0; j < 4; j++)
            wmma::fill_fragment(cf[i][j], 0.0f);

    auto load_stage = [&](int s, int k0) {
        uint32_t abase = smb + (uint32_t)(s * STG) * 2;
        uint32_t bbase = abase + (uint32_t)ATILE * 2;
#pragma unroll
        for (int it = 0; it < 4; it++) {
            int idx = tid + it * 128;
            int arow = idx >> 2, acol = idx & 3;     // A: 128 x 4 chunks
            int brow = idx >> 4, bcol = idx & 15;    // B: 32 x 16 chunks
            CP_ASYNC16(abase + (uint32_t)(arow * AST + acol * 8) * 2,
                       A + (size_t)(bm + arow) * K + k0 + acol * 8);
            CP_ASYNC16(bbase + (uint32_t)(brow * BST + bcol * 8) * 2,
                       B + (size_t)(k0 + brow) * N + bn + bcol * 8);
        }
        CP_COMMIT();
    };

    load_stage(0, 0);
    load_stage(1, BK);

    int st = 0;
    for (int k0 = 0; k0 < K; k0 += BK) {
        CP_WAIT1();
        __syncthreads();
        const __half* As = hsm + st * STG;
        const __half* Bs = As + ATILE;
#pragma unroll
        for (int kk = 0; kk < BK; kk += 16) {
            wmma::fragment<wmma::matrix_a, 16, 16, 16, __half, wmma::row_major> af[4];
            wmma::fragment<wmma::matrix_b, 16, 16, 16, __half, wmma::row_major> bf[4];
#pragma unroll
            for (int i = 0; i < 4; i++)
                wmma::load_matrix_sync(af[i], &As[(wM * 64 + i * 16) * AST + kk], AST);
#pragma unroll
            for (int j = 0; j < 4; j++)
                wmma::load_matrix_sync(bf[j], &Bs[kk * BST + wN * 64 + j * 16], BST);
#pragma unroll
            for (int i = 0; i < 4; i++)
#pragma unroll
                for (int j = 0; j < 4; j++)
                    wmma::mma_sync(cf[i][j], af[i], bf[j], cf[i][j]);
        }
        int kn = k0 + 2 * BK;
        if (kn < K) load_stage(st == 0 ? 2 : st - 1, kn);  // (st+2)%3
        else        CP_COMMIT();   // empty group keeps one-group-per-iter invariant
        st = (st == 2) ? 0 : st + 1;
        __syncthreads();
    }
    CP_WAIT0();
    __syncthreads();

    if (MODE == 1) {
        float* C = (float*)Cv;
#pragma unroll
        for (int i = 0; i < 4; i++)
#pragma unroll
            for (int j = 0; j < 4; j++) {
                size_t row = (size_t)bm + wM * 64 + i * 16;
                size_t col = (size_t)bn + wN * 64 + j * 16;
                wmma::store_matrix_sync(C + row * N + col, cf[i][j], N, wmma::mem_row_major);
            }
    } else {
        // fp16 output + fused RoPE on q/k column bands
        __half* C = (__half*)Cv;
        float* stage = (float*)hsm + wid * 320;  // 16x20 fp32 per warp
        const bool doRope = (bn < 2 * EMB);
        const int row_l = l >> 1;
        const int ch = (l & 1) * 8;
#pragma unroll
        for (int i = 0; i < 4; i++)
#pragma unroll
            for (int j = 0; j < 4; j++) {
                wmma::store_matrix_sync(stage, cf[i][j], 20, wmma::mem_row_major);
                __syncwarp();
                const float* sp = stage + row_l * 20 + ch;
                int grow = bm + wM * 64 + i * 16 + row_l;
                int gcol = bn + wN * 64 + j * 16 + ch;
                __half hbuf[8];
                if (doRope) {
                    int sidx = grow & (SEQ - 1);
                    int d2b = (gcol & 127) >> 1;
#pragma unroll
                    for (int t = 0; t < 4; t++) {
                        float c = fcos[sidx * 64 + d2b + t];
                        float sn = fsin[sidx * 64 + d2b + t];
                        float xr = sp[2 * t], xi = sp[2 * t + 1];
                        hbuf[2 * t]     = __float2half(xr * c - xi * sn);
                        hbuf[2 * t + 1] = __float2half(xr * sn + xi * c);
                    }
                } else {
#pragma unroll
                    for (int t = 0; t < 8; t++)
                        hbuf[t] = __float2half(sp[t]);
                }
                *(uint4*)(C + (size_t)grow * N + gcol) = *(uint4*)hbuf;
                __syncwarp();
            }
    }
}

// ---------------------------------------------------------------------------
// Flash attention, fp16 mma.sync m16n8k16, causal, online softmax.
// ldmatrix.x4 fragment loads; P stays in registers (S-accum layout == PV
// A-operand layout). Inputs fp16 (rope applied), output fp16.
// ---------------------------------------------------------------------------
#define FBQ 128
#define FBK 64
#define QST 136
#define FLASH_SMEM ((FBQ * QST + 2 * FBK * QST) * 2)  // 69632 bytes

__device__ __forceinline__ void mma_f16(float* d,
    uint32_t a0, uint32_t a1, uint32_t a2, uint32_t a3,
    uint32_t b0, uint32_t b1)
{
    asm volatile(
        "mma.sync.aligned.m16n8k16.row.col.f32.f16.f16.f32 "
        "{%0,%1,%2,%3},{%4,%5,%6,%7},{%8,%9},{%0,%1,%2,%3};\n"
        : "+f"(d[0]), "+f"(d[1]), "+f"(d[2]), "+f"(d[3])
        : "r"(a0), "r"(a1), "r"(a2), "r"(a3), "r"(b0), "r"(b1));
}

__device__ __forceinline__ uint32_t packh2(float x, float y) {
    __half2 h = __floats2half2_rn(x, y);
    return *(uint32_t*)&h;
}

__global__ void __launch_bounds__(256, 2) flash_f16_kernel(
    const __half* __restrict__ qkv, __half* __restrict__ y)
{
    extern __shared__ __half fsm[];
    __half* qs = fsm;                       // 128 x 136
    __half* ks = qs + FBQ * QST;            // 64 x 136
    __half* vs = ks + FBK * QST;            // 64 x 136

    const int tid = threadIdx.x;
    const int w = tid >> 5;
    const int l = tid & 31;
    const int lq = l >> 2;
    const int lr = l & 3;
    const int qt = blockIdx.x;
    const int h = blockIdx.y;
    const int b = blockIdx.z;
    const int q0 = qt * FBQ;

    const size_t rs = 3 * EMB;
    const __half* qb  = qkv + (size_t)(b * SEQ + q0) * rs + h * HEAD_DIM;
    const __half* kb0 = qkv + (size_t)(b * SEQ) * rs + EMB + h * HEAD_DIM;
    const __half* vb0 = kb0 + EMB;

    const uint32_t qsu = smem_u32(qs);
    const uint32_t ksu = smem_u32(ks);
    const uint32_t vsu = smem_u32(vs);

    // ldmatrix lane-address bases (bytes)
    const uint32_t qbase = qsu + (uint32_t)(((w * 16 + (l & 15)) * QST + ((l >> 4) << 3)) * 2);
    const uint32_t kbase = ksu + (uint32_t)(((((l & 7) + ((l >> 4) << 3)) * QST) + (((l >> 3) & 1) << 3)) * 2);
    const uint32_t vbase = vsu + (uint32_t)((((l & 15) * QST) + ((l >> 4) << 3)) * 2);

    // stage Q: 128 rows x 16 chunks of 8 halves
#pragma unroll
    for (int i = 0; i < 8; i++) {
        int idx = tid + i * 256;
        int row = idx >> 4, c = idx & 15;
        *(uint4*)&qs[row * QST + c * 8] = *(const uint4*)(qb + (size_t)row * rs + c * 8);
    }

    float d[16][4];
#pragma unroll
    for (int nt = 0; nt < 16; nt++)
#pragma unroll
        for (int c = 0; c < 4; c++)
            d[nt][c] = 0.0f;

    float m0 = -INFINITY, m1 = -INFINITY, l0 = 0.0f, l1 = 0.0f;
    const float sc = 0.08838834764831845f;  // 1/sqrt(128)
    const int ktmax = 2 * qt + 1;
    const int myrowmax = q0 + w * 16 + 15;
    const int arow = w * 16 + lq;

    for (int kt = 0; kt <= ktmax; kt++) {
        __syncthreads();
        const __half* kb = kb0 + (size_t)kt * FBK * rs;
        const __half* vb = vb0 + (size_t)kt * FBK * rs;
#pragma unroll
        for (int i = 0; i < 4; i++) {
            int idx = tid + i * 256;
            int row = idx >> 4, c = idx & 15;
            *(uint4*)&ks[row * QST + c * 8] = *(const uint4*)(kb + (size_t)row * rs + c * 8);
            *(uint4*)&vs[row * QST + c * 8] = *(const uint4*)(vb + (size_t)row * rs + c * 8);
        }
        __syncthreads();

        const bool active = (kt * FBK <= myrowmax);
        if (active) {
            // ---- S = Q @ K^T (ldmatrix.x4 fragments) ----
            float s[8][4];
#pragma unroll
            for (int nt = 0; nt < 8; nt++)
#pragma unroll
                for (int c = 0; c < 4; c++)
                    s[nt][c] = 0.0f;

#pragma unroll
            for (int k = 0; k < 8; k++) {
                uint32_t a0, a1, a2, a3;
                LDSM_X4(a0, a1, a2, a3, qbase + k * 32);
#pragma unroll
                for (int ntp = 0; ntp < 4; ntp++) {
                    uint32_t b0, b1, b2, b3;
                    LDSM_X4(b0, b1, b2, b3, kbase + (uint32_t)(ntp * 16 * QST * 2) + k * 32);
                    mma_f16(s[2 * ntp],     a0, a1, a2, a3, b0, b1);
                    mma_f16(s[2 * ntp + 1], a0, a1, a2, a3, b2, b3);
                }
            }

            // ---- scale + causal mask ----
            const bool domask = (kt >= 2 * qt);
#pragma unroll
            for (int nt = 0; nt < 8; nt++)
#pragma unroll
                for (int c = 0; c < 4; c++) {
                    float v = s[nt][c] * sc;
                    if (domask) {
                        int kg = kt * FBK + nt * 8 + 2 * lr + (c & 1);
                        int rg = q0 + arow + ((c >= 2) ? 8 : 0);
                        if (kg > rg) v = -INFINITY;
                    }
                    s[nt][c] = v;
                }

            // ---- online softmax (rows arow, arow+8) ----
            float mx0 = -INFINITY, mx1 = -INFINITY;
#pragma unroll
            for (int nt = 0; nt < 8; nt++) {
                mx0 = fmaxf(mx0, fmaxf(s[nt][0], s[nt][1]));
                mx1 = fmaxf(mx1, fmaxf(s[nt][2], s[nt][3]));
            }
            mx0 = fmaxf(mx0, __shfl_xor_sync(0xffffffffu, mx0, 1));
            mx0 = fmaxf(mx0, __shfl_xor_sync(0xffffffffu, mx0, 2));
            mx1 = fmaxf(mx1, __shfl_xor_sync(0xffffffffu, mx1, 1));
            mx1 = fmaxf(mx1, __shfl_xor_sync(0xffffffffu, mx1, 2));

            float nm0 = fmaxf(m0, mx0), nm1 = fmaxf(m1, mx1);
            float al0 = __expf(m0 - nm0), al1 = __expf(m1 - nm1);
            m0 = nm0; m1 = nm1;

            float sum0 = 0.0f, sum1 = 0.0f;
#pragma unroll
            for (int nt = 0; nt < 8; nt++) {
                float p0 = __expf(s[nt][0] - nm0);
                float p1 = __expf(s[nt][1] - nm0);
                float p2 = __expf(s[nt][2] - nm1);
                float p3 = __expf(s[nt][3] - nm1);
                s[nt][0] = p0; s[nt][1] = p1; s[nt][2] = p2; s[nt][3] = p3;
                sum0 += p0 + p1; sum1 += p2 + p3;
            }
            sum0 += __shfl_xor_sync(0xffffffffu, sum0, 1);
            sum0 += __shfl_xor_sync(0xffffffffu, sum0, 2);
            sum1 += __shfl_xor_sync(0xffffffffu, sum1, 1);
            sum1 += __shfl_xor_sync(0xffffffffu, sum1, 2);
            l0 = l0 * al0 + sum0;
            l1 = l1 * al1 + sum1;

#pragma unroll
            for (int nt = 0; nt < 16; nt++) {
                d[nt][0] *= al0; d[nt][1] *= al0;
                d[nt][2] *= al1; d[nt][3] *= al1;
            }

            // ---- O += P @ V : P fragments already live in s[] registers ----
#pragma unroll
            for (int kbk = 0; kbk < 4; kbk++) {
                uint32_t a0 = packh2(s[2 * kbk][0],     s[2 * kbk][1]);
                uint32_t a1 = packh2(s[2 * kbk][2],     s[2 * kbk][3]);
                uint32_t a2 = packh2(s[2 * kbk + 1][0], s[2 * kbk + 1][1]);
                uint32_t a3 = packh2(s[2 * kbk + 1][2], s[2 * kbk + 1][3]);
#pragma unroll
                for (int ntp = 0; ntp < 8; ntp++) {
                    uint32_t b0, b1, b2, b3;
                    LDSM_X4_T(b0, b1, b2, b3,
                              vbase + (uint32_t)(kbk * 16 * QST * 2) + ntp * 32);
                    mma_f16(d[2 * ntp],     a0, a1, a2, a3, b0, b1);
                    mma_f16(d[2 * ntp + 1], a0, a1, a2, a3, b2, b3);
                }
            }
        }
    }

    // epilogue: divide by l, write fp16 y
    float inv0 = 1.0f / l0, inv1 = 1.0f / l1;
    __half* yb  = y + (size_t)(b * SEQ + q0 + arow) * EMB + h * HEAD_DIM;
    __half* yb2 = yb + (size_t)8 * EMB;
#pragma unroll
    for (int nt = 0; nt < 16; nt++) {
        __half2 o0 = __floats2half2_rn(d[nt][0] * inv0, d[nt][1] * inv0);
        __half2 o1 = __floats2half2_rn(d[nt][2] * inv1, d[nt][3] * inv1);
        *(__half2*)&yb[nt * 8 + 2 * lr]  = o0;
        *(__half2*)&yb2[nt * 8 + 2 * lr] = o1;
    }
}

// ---------------------------------------------------------------------------
// Launch
// ---------------------------------------------------------------------------
extern "C" void kernel_launch(void* const* d_in, const int* in_sizes, int n_in,
                              void* d_out, int out_size)
{
    const float* x       = (const float*)d_in[0];
    const float* w_atten = (const float*)d_in[1];
    const float* w_proj  = (const float*)d_in[2];
    const float* fcos    = (const float*)d_in[3];
    const float* fsin    = (const float*)d_in[4];
    float* out = (float*)d_out;

    __half *qkv16 = nullptr, *y16 = nullptr, *a16 = nullptr, *b16 = nullptr;
    cudaGetSymbolAddress((void**)&qkv16, g_qkv16);
    cudaGetSymbolAddress((void**)&y16, g_y16);
    cudaGetSymbolAddress((void**)&a16, g_a16);
    cudaGetSymbolAddress((void**)&b16, g_b16);

    cudaFuncSetAttribute(gemm_f16_kernel<0>, cudaFuncAttributeMaxDynamicSharedMemorySize,
                         GEMM_SMEM);
    cudaFuncSetAttribute(gemm_f16_kernel<1>, cudaFuncAttributeMaxDynamicSharedMemorySize,
                         GEMM_SMEM);
    cudaFuncSetAttribute(flash_f16_kernel, cudaFuncAttributeMaxDynamicSharedMemorySize,
                         FLASH_SMEM);

    const int MROWS = BATCH * SEQ;                    // 4096
    const size_t NE = (size_t)MROWS * EMB;            // 16.7M
    const size_t NW1 = (size_t)EMB * 3 * EMB;         // 50.3M

    // 1) convert x and w_atten to fp16
    cvt16_kernel<<<(int)(NE / 2048), 256>>>(x, a16);
    cvt16_kernel<<<(int)(NW1 / 2048), 256>>>(w_atten, b16);

    // 2) qkv16 = rope(x @ w_atten) — fused epilogue
    {
        dim3 grid((3 * EMB) / BN, MROWS / BM);
        gemm_f16_kernel<0><<<grid, 128, GEMM_SMEM>>>(a16, b16, qkv16, fcos, fsin,
                                                     MROWS, 3 * EMB, EMB);
    }

    // 3) flash attention -> y16
    {
        dim3 grid(SEQ / FBQ, NUM_HEADS, BATCH);
        flash_f16_kernel<<<grid, 256, FLASH_SMEM>>>(qkv16, y16);
    }

    // 4) convert w_proj, then out = y @ w_proj (fp32 out)
    cvt16_kernel<<<(int)(NE / 2048), 256>>>(w_proj, b16);
    {
        dim3 grid(EMB / BN, MROWS / BM);
        gemm_f16_kernel<1><<<grid, 128, GEMM_SMEM>>>(y16, b16, out, nullptr, nullptr,
                                                     MROWS, EMB, EMB);
    }
}